// round 16
// baseline (speedup 1.0000x reference)
#include <cuda_runtime.h>
#include <cuda_fp16.h>
#include <cstdint>

#define N_NODES    50000
#define N_EDGES    800000
#define NUM_GRAPHS 500
#define CONV_OUT   128
#define HCAT       384
#define KPAD       192
#define STRIDE12   192

// ---------------- scratch (static device globals) ----------------
__device__ __half    d_projLh[N_NODES * CONV_OUT];   // fp16 projL (gather operand)
__device__ __half    d_projRh[N_NODES * CONV_OUT];   // fp16 projR
__device__ int       d_count[N_NODES];
__device__ int       d_rowptr[N_NODES + 1];
__device__ int       d_cursor[N_NODES];
__device__ int       d_adj[N_EDGES];
__device__ unsigned  d_genc[NUM_GRAPHS * HCAT];
__device__ __half    d_B[3 * 256 * KPAD];          // [layer][n][k], fp16, zero-padded k>=K
__device__ __half    d_A0[N_NODES * 128];          // layer0 A (fp16)
__device__ __half    d_A12[N_NODES * STRIDE12];    // layers1-2 A (fp16), cols 160-191 zeroed

// monotone float <-> uint encoding for atomicMax on signed floats
__device__ __forceinline__ unsigned encf(float f) {
    unsigned u = __float_as_uint(f);
    return (u & 0x80000000u) ? ~u : (u | 0x80000000u);
}
__device__ __forceinline__ float decf(unsigned u) {
    u = (u & 0x80000000u) ? (u & 0x7FFFFFFFu) : ~u;
    return __uint_as_float(u);
}
#define ENC_NEG_INF 0x007FFFFFu

__device__ __forceinline__ uint32_t smem_u32(const void* p) {
    uint32_t a;
    asm("{ .reg .u64 t; cvta.to.shared.u64 t, %1; cvt.u32.u64 %0, t; }" : "=r"(a) : "l"(p));
    return a;
}

__device__ __forceinline__ void cp16(uint32_t dst, const void* src, bool pred) {
    int sz = pred ? 16 : 0;
    asm volatile("cp.async.cg.shared.global [%0], [%1], 16, %2;"
                 :: "r"(dst), "l"(src), "r"(sz) : "memory");
}
#define CP_COMMIT()  asm volatile("cp.async.commit_group;" ::: "memory")
#define CP_WAIT(n)   asm volatile("cp.async.wait_group %0;" :: "n"(n) : "memory")

#define LDSM_X4(r, addr) \
    asm volatile("ldmatrix.sync.aligned.m8n8.x4.shared.b16 {%0,%1,%2,%3}, [%4];" \
        : "=r"((r)[0]), "=r"((r)[1]), "=r"((r)[2]), "=r"((r)[3]) : "r"(addr))

#define MMA_F16(c, a, b0, b1) \
    asm volatile("mma.sync.aligned.m16n8k16.row.col.f32.f16.f16.f32 " \
        "{%0,%1,%2,%3}, {%4,%5,%6,%7}, {%8,%9}, {%0,%1,%2,%3};" \
        : "+f"((c)[0]), "+f"((c)[1]), "+f"((c)[2]), "+f"((c)[3]) \
        : "r"((a)[0]), "r"((a)[1]), "r"((a)[2]), "r"((a)[3]), "r"(b0), "r"(b1))

// ---------------- fused prep (half2-vectorized A regions) ----------------
#define RP0 (N_NODES * 64)        // A0: 128 cols / 2 per thread
#define RP1 (N_NODES * 32)        // A12 cols 128..191 / 2 per thread (info + zero pad)
#define RP2 (3 * 256 * KPAD)
#define RP3 (NUM_GRAPHS * HCAT)
#define RP4 (N_NODES)
#define PREP_TOTAL (RP0 + RP1 + RP2 + RP3 + RP4)

__global__ void prep_fused(const float* __restrict__ x, const float* __restrict__ info,
                           const int* __restrict__ batch,
                           const float* __restrict__ Wl0, const float* __restrict__ Wr0,
                           const float* __restrict__ Wl1, const float* __restrict__ Wr1,
                           const float* __restrict__ Wl2, const float* __restrict__ Wr2) {
    long long i = (long long)blockIdx.x * blockDim.x + threadIdx.x;
    if (i < RP0) {
        int r = (int)(i >> 6), c = (int)(i & 63) * 2;   // c even, pair {c, c+1}
        float2 v;
        if (c < 96) v = *(const float2*)&x[r * 96 + c];
        else        v = *(const float2*)&info[batch[r] * 32 + (c - 96)];
        *(__half2*)&d_A0[(size_t)r * 128 + c] = __floats2half2_rn(v.x, v.y);
        return;
    }
    i -= RP0;
    if (i < RP1) {
        int r = (int)(i >> 5), c = (int)(i & 31) * 2;   // c in 0..62, col = 128+c
        float2 v = make_float2(0.f, 0.f);
        if (c < 32) v = *(const float2*)&info[batch[r] * 32 + c];
        *(__half2*)&d_A12[(size_t)r * STRIDE12 + 128 + c] = __floats2half2_rn(v.x, v.y);
        return;
    }
    i -= RP1;
    if (i < RP2) {
        int idx = (int)i;
        int layer = idx / (256 * KPAD);
        int rem = idx - layer * (256 * KPAD);
        int n = rem / KPAD, k = rem - n * KPAD;
        int K = (layer == 0) ? 128 : 160;
        const float* Wl = (layer == 0) ? Wl0 : (layer == 1) ? Wl1 : Wl2;
        const float* Wr = (layer == 0) ? Wr0 : (layer == 1) ? Wr1 : Wr2;
        float v = 0.f;
        if (k < K) v = (n < 128) ? Wl[k * 128 + n] : Wr[k * 128 + (n - 128)];
        d_B[idx] = __float2half(v);
        return;
    }
    i -= RP2;
    if (i < RP3) { d_genc[i] = ENC_NEG_INF; return; }
    i -= RP3;
    if (i < RP4) d_count[i] = 0;
}

// ---------------- graph-structure kernels (scalar: 1 edge/thread) ----------------
__global__ void deg_kernel(const int* __restrict__ dst) {
    int e = blockIdx.x * blockDim.x + threadIdx.x;
    if (e < N_EDGES) atomicAdd(&d_count[dst[e]], 1);
}

__global__ void scan_kernel() {
    __shared__ int s[1024];
    int t = threadIdx.x;
    const int CH = (N_NODES + 1023) / 1024;
    int base = t * CH;
    int lim = min(base + CH, N_NODES);
    int sum = 0;
    for (int i = base; i < lim; i++) sum += d_count[i];
    s[t] = sum;
    __syncthreads();
    for (int off = 1; off < 1024; off <<= 1) {
        int v = (t >= off) ? s[t - off] : 0;
        __syncthreads();
        s[t] += v;
        __syncthreads();
    }
    int run = s[t] - sum;
    for (int i = base; i < lim; i++) {
        d_rowptr[i] = run;
        d_cursor[i] = run;
        run += d_count[i];
    }
    if (t == 1023) d_rowptr[N_NODES] = s[1023];
}

__global__ void fill_kernel(const int* __restrict__ src, const int* __restrict__ dst) {
    int e = blockIdx.x * blockDim.x + threadIdx.x;
    if (e < N_EDGES) {
        int pos = atomicAdd(&d_cursor[dst[e]], 1);
        d_adj[pos] = src[e];
    }
}

// ---------------- fp16 single-term mma.sync GEMM, chunk 64, 3-stage pipeline ----------------
// C[M,256] = A @ Wcat; grid.y selects N-half (0->projL, 1->projR), both fp16 out
// CTA: 128x128, 8 warps (4M x 2N), warp 32x64. K chunk 64.
#define PITCH 144
#define ST_A   0
#define ST_B   18432
#define STAGE  36864
#define SM_TOTAL 110592

__global__ void __launch_bounds__(256, 2)
sage_gemm(const __half* __restrict__ A, const __half* __restrict__ B,
          int strideA, int nch) {
    extern __shared__ char smem[];
    uint32_t sb = smem_u32(smem);
    const int M = N_NODES;
    int bm = blockIdx.x * 128;
    int nh = blockIdx.y;
    int tid = threadIdx.x;
    int wid = tid >> 5;
    int lane = tid & 31;
    int wm = wid & 3, wn = wid >> 2;
    int g = lane >> 2, t4 = lane & 3;

    const char* Ag = (const char*)A;
    const char* Bg = (const char*)B;

    float acc[2][8][4];
#pragma unroll
    for (int mt = 0; mt < 2; mt++)
#pragma unroll
        for (int nt = 0; nt < 8; nt++)
#pragma unroll
            for (int j = 0; j < 4; j++) acc[mt][nt][j] = 0.f;

    // per-thread load coords: 1024 (row, seg16) pairs over 256 threads -> 4 iters
    auto load_chunk = [&](int s, int kc) {
        int c0 = kc * 64;
        uint32_t st = sb + s * STAGE;
#pragma unroll
        for (int it = 0; it < 4; it++) {
            int idx = tid + it * 256;
            int r = idx >> 3, seg = idx & 7;
            int row = bm + r;
            bool p = row < M;
            size_t aoff = ((size_t)row * strideA + c0) * 2 + seg * 16;
            uint32_t so = r * PITCH + seg * 16;
            cp16(st + ST_A + so, Ag + aoff, p);
            size_t boff = ((size_t)(nh * 128 + r) * KPAD + c0) * 2 + seg * 16;
            cp16(st + ST_B + so, Bg + boff, true);
        }
    };

    load_chunk(0, 0);
    CP_COMMIT();
    if (nch > 1) load_chunk(1, 1);
    CP_COMMIT();

    uint32_t brow = (lane & 7) + ((lane >> 4) << 3);
    uint32_t bkof = ((lane >> 3) & 1) << 4;

    for (int kc = 0; kc < nch; kc++) {
        if (kc + 1 < nch) {
            CP_WAIT(1);
        } else {
            CP_WAIT(0);
        }
        __syncthreads();
        if (kc + 2 < nch) {
            load_chunk((kc + 2) % 3, kc + 2);
            CP_COMMIT();
        }

        uint32_t st = sb + (kc % 3) * STAGE;
#pragma unroll
        for (int kk = 0; kk < 4; kk++) {
            uint32_t afr[2][4], bfr[4][4];
#pragma unroll
            for (int mt = 0; mt < 2; mt++) {
                uint32_t ab = (uint32_t)((wm * 32 + mt * 16 + (lane & 15)) * PITCH
                               + kk * 32 + ((lane >> 4) << 4));
                LDSM_X4(afr[mt], st + ST_A + ab);
            }
#pragma unroll
            for (int nt2 = 0; nt2 < 4; nt2++) {
                uint32_t bb = (uint32_t)((wn * 64 + nt2 * 16 + brow) * PITCH + kk * 32 + bkof);
                LDSM_X4(bfr[nt2], st + ST_B + bb);
            }
#pragma unroll
            for (int mt = 0; mt < 2; mt++)
#pragma unroll
                for (int nt = 0; nt < 8; nt++) {
                    uint32_t b0 = bfr[nt >> 1][(nt & 1) * 2];
                    uint32_t b1 = bfr[nt >> 1][(nt & 1) * 2 + 1];
                    MMA_F16(acc[mt][nt], afr[mt], b0, b1);
                }
        }
        __syncthreads();
    }

    // epilogue: fp16 stores for both halves
    __half* outp = (nh == 0) ? d_projLh : d_projRh;
#pragma unroll
    for (int mt = 0; mt < 2; mt++) {
        int r0 = bm + wm * 32 + mt * 16 + g;
#pragma unroll
        for (int nt = 0; nt < 8; nt++) {
            int col = wn * 64 + nt * 8 + t4 * 2;
            if (r0 < M)
                *(__half2*)&outp[(size_t)r0 * 128 + col] =
                    __floats2half2_rn(acc[mt][nt][0], acc[mt][nt][1]);
            if (r0 + 8 < M)
                *(__half2*)&outp[(size_t)(r0 + 8) * 128 + col] =
                    __floats2half2_rn(acc[mt][nt][2], acc[mt][nt][3]);
        }
    }
}

// ---------------- aggregation + pooling (+ next-layer A write) ----------------
#define GNODES 16
__global__ void __launch_bounds__(512)
gather_combine(const float* __restrict__ b, const int* __restrict__ batch,
               int layer, int write_a) {
    __shared__ float sv[GNODES][CONV_OUT];
    __shared__ int   sbat[GNODES];

    int tid = threadIdx.x;
    int wid = tid >> 5;
    int lane = tid & 31;
    int node = blockIdx.x * GNODES + wid;
    bool valid = (node < N_NODES);

    if (valid) {
        int s0 = d_rowptr[node];
        int s1 = d_rowptr[node + 1];

        float acc0 = 0.f, acc1 = 0.f, acc2 = 0.f, acc3 = 0.f;
#pragma unroll 4
        for (int j = s0; j < s1; j++) {
            int nb = d_adj[j];
            uint2 v = *(const uint2*)&d_projLh[(size_t)nb * 128 + lane * 4];
            float2 f0 = __half22float2(*(__half2*)&v.x);
            float2 f1 = __half22float2(*(__half2*)&v.y);
            acc0 += f0.x; acc1 += f0.y; acc2 += f1.x; acc3 += f1.y;
        }
        float inv = 1.0f / fmaxf((float)(s1 - s0), 1.0f);
        uint2 rv = *(const uint2*)&d_projRh[(size_t)node * 128 + lane * 4];
        float2 r0 = __half22float2(*(__half2*)&rv.x);
        float2 r1 = __half22float2(*(__half2*)&rv.y);
        float4 bb = *(const float4*)&b[lane * 4];
        float hv[4];
        hv[0] = acc0 * inv + r0.x + bb.x;
        hv[1] = acc1 * inv + r0.y + bb.y;
        hv[2] = acc2 * inv + r1.x + bb.z;
        hv[3] = acc3 * inv + r1.y + bb.w;

        if (write_a) {
            __half2 h0 = __floats2half2_rn(hv[0], hv[1]);
            __half2 h1 = __floats2half2_rn(hv[2], hv[3]);
            size_t off = (size_t)node * STRIDE12 + lane * 4;
            *(__half2*)&d_A12[off]     = h0;
            *(__half2*)&d_A12[off + 2] = h1;
        }

        *(float4*)&sv[wid][lane * 4] = make_float4(hv[0], hv[1], hv[2], hv[3]);
        if (lane == 0) sbat[wid] = batch[node];
    } else {
        if (lane == 0) sbat[wid] = -1;
    }
    __syncthreads();

    if (tid < CONV_OUT) {
        int col = tid;
        int cur = -1;
        float mx = 0.f;
#pragma unroll
        for (int i = 0; i < GNODES; i++) {
            int bt = sbat[i];
            if (bt != cur) {
                if (cur >= 0)
                    atomicMax(&d_genc[cur * HCAT + layer * 128 + col], encf(mx));
                cur = bt;
                mx = -3.4e38f;
            }
            if (bt >= 0) mx = fmaxf(mx, sv[i][col]);
        }
        if (cur >= 0)
            atomicMax(&d_genc[cur * HCAT + layer * 128 + col], encf(mx));
    }
}

// ---------------- FC head ----------------
__global__ void fc_kernel(const float* __restrict__ Wfc1, const float* __restrict__ bfc1,
                          const float* __restrict__ Wfc2, const float* __restrict__ bfc2,
                          float* __restrict__ out) {
    __shared__ float g[HCAT];
    __shared__ float z[160];
    int gr = blockIdx.x, t = threadIdx.x;

    for (int i = t; i < HCAT; i += 160) g[i] = decf(d_genc[gr * HCAT + i]);
    __syncthreads();

    float acc = bfc1[t];
#pragma unroll 8
    for (int k = 0; k < HCAT; k++) acc += g[k] * Wfc1[k * 160 + t];
    z[t] = fmaxf(acc, 0.f);
    __syncthreads();

    if (t < 10) {
        float o = bfc2[t];
#pragma unroll 8
        for (int k = 0; k < 160; k++) o += z[k] * Wfc2[k * 10 + t];
        out[gr * 10 + t] = o;
    }
}

// ---------------- launch ----------------
extern "C" void kernel_launch(void* const* d_in, const int* in_sizes, int n_in,
                              void* d_out, int out_size) {
    const float* x     = (const float*)d_in[0];
    const int*   eidx  = (const int*)d_in[1];
    const int*   batch = (const int*)d_in[2];
    const float* info  = (const float*)d_in[3];
    const float* Wl[3] = { (const float*)d_in[4], (const float*)d_in[7],  (const float*)d_in[10] };
    const float* Wr[3] = { (const float*)d_in[5], (const float*)d_in[8],  (const float*)d_in[11] };
    const float* bb[3] = { (const float*)d_in[6], (const float*)d_in[9],  (const float*)d_in[12] };
    const float* Wfc1  = (const float*)d_in[13];
    const float* bfc1  = (const float*)d_in[14];
    const float* Wfc2  = (const float*)d_in[15];
    const float* bfc2  = (const float*)d_in[16];
    float* out = (float*)d_out;

    const int* src = eidx;
    const int* dst = eidx + N_EDGES;
    const int T = 256;

    cudaFuncSetAttribute(sage_gemm, cudaFuncAttributeMaxDynamicSharedMemorySize, SM_TOTAL);

    prep_fused<<<(int)((PREP_TOTAL + T - 1) / T), T>>>(x, info, batch,
        Wl[0], Wr[0], Wl[1], Wr[1], Wl[2], Wr[2]);
    deg_kernel<<<(N_EDGES + T - 1) / T, T>>>(dst);
    scan_kernel<<<1, 1024>>>();
    fill_kernel<<<(N_EDGES + T - 1) / T, T>>>(src, dst);

    __half *a0 = nullptr, *a12 = nullptr, *bp = nullptr;
    cudaGetSymbolAddress((void**)&a0, d_A0);
    cudaGetSymbolAddress((void**)&a12, d_A12);
    cudaGetSymbolAddress((void**)&bp, d_B);

    for (int layer = 0; layer < 3; layer++) {
        int nch = (layer == 0) ? 2 : 3;        // chunk=64; layers 1-2 zero-padded to 192
        const __half* A = (layer == 0) ? a0 : a12;
        int strideA = (layer == 0) ? 128 : STRIDE12;

        sage_gemm<<<dim3((N_NODES + 127) / 128, 2), 256, SM_TOTAL>>>(
            A, bp + layer * 256 * KPAD, strideA, nch);

        gather_combine<<<(N_NODES + GNODES - 1) / GNODES, 512>>>(bb[layer], batch, layer, layer < 2);
    }

    fc_kernel<<<NUM_GRAPHS, 160>>>(Wfc1, bfc1, Wfc2, bfc2, out);
    (void)in_sizes; (void)n_in; (void)out_size;
}

// round 17
// speedup vs baseline: 1.0047x; 1.0047x over previous
#include <cuda_runtime.h>
#include <cuda_fp16.h>
#include <cstdint>

#define N_NODES    50000
#define N_EDGES    800000
#define NUM_GRAPHS 500
#define CONV_OUT   128
#define HCAT       384
#define KPAD       192
#define STRIDE12   192

// ---------------- scratch (static device globals) ----------------
__device__ __half    d_projLh[N_NODES * CONV_OUT];   // fp16 projL (gather operand)
__device__ __half    d_projRh[N_NODES * CONV_OUT];   // fp16 projR
__device__ int       d_count[N_NODES];
__device__ int       d_rowptr[N_NODES + 1];
__device__ int       d_cursor[N_NODES];
__device__ int       d_adj[N_EDGES];
__device__ unsigned  d_genc[NUM_GRAPHS * HCAT];
__device__ __half    d_B[3 * 256 * KPAD];          // [layer][n][k], fp16
__device__ __half    d_A0[N_NODES * 128];          // layer0 A (fp16)
__device__ __half    d_A12[N_NODES * STRIDE12];    // layers1-2 A (fp16)

// monotone float <-> uint encoding for atomicMax on signed floats
__device__ __forceinline__ unsigned encf(float f) {
    unsigned u = __float_as_uint(f);
    return (u & 0x80000000u) ? ~u : (u | 0x80000000u);
}
__device__ __forceinline__ float decf(unsigned u) {
    u = (u & 0x80000000u) ? (u & 0x7FFFFFFFu) : ~u;
    return __uint_as_float(u);
}
#define ENC_NEG_INF 0x007FFFFFu

__device__ __forceinline__ uint32_t smem_u32(const void* p) {
    uint32_t a;
    asm("{ .reg .u64 t; cvta.to.shared.u64 t, %1; cvt.u32.u64 %0, t; }" : "=r"(a) : "l"(p));
    return a;
}

__device__ __forceinline__ void cp16(uint32_t dst, const void* src, bool pred) {
    int sz = pred ? 16 : 0;
    asm volatile("cp.async.cg.shared.global [%0], [%1], 16, %2;"
                 :: "r"(dst), "l"(src), "r"(sz) : "memory");
}
#define CP_COMMIT()  asm volatile("cp.async.commit_group;" ::: "memory")
#define CP_WAIT(n)   asm volatile("cp.async.wait_group %0;" :: "n"(n) : "memory")

#define LDSM_X4(r, addr) \
    asm volatile("ldmatrix.sync.aligned.m8n8.x4.shared.b16 {%0,%1,%2,%3}, [%4];" \
        : "=r"((r)[0]), "=r"((r)[1]), "=r"((r)[2]), "=r"((r)[3]) : "r"(addr))

#define MMA_F16(c, a, b0, b1) \
    asm volatile("mma.sync.aligned.m16n8k16.row.col.f32.f16.f16.f32 " \
        "{%0,%1,%2,%3}, {%4,%5,%6,%7}, {%8,%9}, {%0,%1,%2,%3};" \
        : "+f"((c)[0]), "+f"((c)[1]), "+f"((c)[2]), "+f"((c)[3]) \
        : "r"((a)[0]), "r"((a)[1]), "r"((a)[2]), "r"((a)[3]), "r"(b0), "r"(b1))

// ---------------- fused prep (half2-vectorized A regions) ----------------
#define RP0 (N_NODES * 64)        // A0: 128 cols / 2 per thread
#define RP1 (N_NODES * 16)        // A12 info cols 128..159 / 2 per thread
#define RP2 (3 * 256 * KPAD)
#define RP3 (NUM_GRAPHS * HCAT)
#define RP4 (N_NODES)
#define PREP_TOTAL (RP0 + RP1 + RP2 + RP3 + RP4)

__global__ void prep_fused(const float* __restrict__ x, const float* __restrict__ info,
                           const int* __restrict__ batch,
                           const float* __restrict__ Wl0, const float* __restrict__ Wr0,
                           const float* __restrict__ Wl1, const float* __restrict__ Wr1,
                           const float* __restrict__ Wl2, const float* __restrict__ Wr2) {
    long long i = (long long)blockIdx.x * blockDim.x + threadIdx.x;
    if (i < RP0) {
        int r = (int)(i >> 6), c = (int)(i & 63) * 2;
        float2 v;
        if (c < 96) v = *(const float2*)&x[r * 96 + c];
        else        v = *(const float2*)&info[batch[r] * 32 + (c - 96)];
        *(__half2*)&d_A0[(size_t)r * 128 + c] = __floats2half2_rn(v.x, v.y);
        return;
    }
    i -= RP0;
    if (i < RP1) {
        int r = (int)(i >> 4), c = (int)(i & 15) * 2;
        float2 v = *(const float2*)&info[batch[r] * 32 + c];
        *(__half2*)&d_A12[(size_t)r * STRIDE12 + 128 + c] = __floats2half2_rn(v.x, v.y);
        return;
    }
    i -= RP1;
    if (i < RP2) {
        int idx = (int)i;
        int layer = idx / (256 * KPAD);
        int rem = idx - layer * (256 * KPAD);
        int n = rem / KPAD, k = rem - n * KPAD;
        int K = (layer == 0) ? 128 : 160;
        const float* Wl = (layer == 0) ? Wl0 : (layer == 1) ? Wl1 : Wl2;
        const float* Wr = (layer == 0) ? Wr0 : (layer == 1) ? Wr1 : Wr2;
        float v = 0.f;
        if (k < K) v = (n < 128) ? Wl[k * 128 + n] : Wr[k * 128 + (n - 128)];
        d_B[idx] = __float2half(v);
        return;
    }
    i -= RP2;
    if (i < RP3) { d_genc[i] = ENC_NEG_INF; return; }
    i -= RP3;
    if (i < RP4) d_count[i] = 0;
}

// ---------------- graph-structure kernels (scalar: 1 edge/thread) ----------------
__global__ void deg_kernel(const int* __restrict__ dst) {
    int e = blockIdx.x * blockDim.x + threadIdx.x;
    if (e < N_EDGES) atomicAdd(&d_count[dst[e]], 1);
}

__global__ void scan_kernel() {
    __shared__ int s[1024];
    int t = threadIdx.x;
    const int CH = (N_NODES + 1023) / 1024;
    int base = t * CH;
    int lim = min(base + CH, N_NODES);
    int sum = 0;
    for (int i = base; i < lim; i++) sum += d_count[i];
    s[t] = sum;
    __syncthreads();
    for (int off = 1; off < 1024; off <<= 1) {
        int v = (t >= off) ? s[t - off] : 0;
        __syncthreads();
        s[t] += v;
        __syncthreads();
    }
    int run = s[t] - sum;
    for (int i = base; i < lim; i++) {
        d_rowptr[i] = run;
        d_cursor[i] = run;
        run += d_count[i];
    }
    if (t == 1023) d_rowptr[N_NODES] = s[1023];
}

__global__ void fill_kernel(const int* __restrict__ src, const int* __restrict__ dst) {
    int e = blockIdx.x * blockDim.x + threadIdx.x;
    if (e < N_EDGES) {
        int pos = atomicAdd(&d_cursor[dst[e]], 1);
        d_adj[pos] = src[e];
    }
}

// ---------------- fp16 single-term mma.sync GEMM, chunk 32, 3-stage pipeline ----------------
// C[M,256] = A @ Wcat; grid.y selects N-half (0->projL, 1->projR), both fp16 out
// CTA: 128x128, 8 warps (4M x 2N), warp 32x64. K chunk 32, exact K.
#define PITCH 80
#define ST_A   0
#define ST_B   10240
#define STAGE  20480
#define SM_TOTAL 61440

__global__ void __launch_bounds__(256, 2)
sage_gemm(const __half* __restrict__ A, const __half* __restrict__ B,
          int strideA, int nch) {
    extern __shared__ char smem[];
    uint32_t sb = smem_u32(smem);
    const int M = N_NODES;
    int bm = blockIdx.x * 128;
    int nh = blockIdx.y;
    int tid = threadIdx.x;
    int wid = tid >> 5;
    int lane = tid & 31;
    int wm = wid & 3, wn = wid >> 2;
    int g = lane >> 2, t4 = lane & 3;

    const char* Ag = (const char*)A;
    const char* Bg = (const char*)B;

    int r0i = tid >> 2, seg = tid & 3;
    int r1i = r0i + 64;
    bool p0 = (bm + r0i) < M;
    bool p1 = (bm + r1i) < M;

    float acc[2][8][4];
#pragma unroll
    for (int mt = 0; mt < 2; mt++)
#pragma unroll
        for (int nt = 0; nt < 8; nt++)
#pragma unroll
            for (int j = 0; j < 4; j++) acc[mt][nt][j] = 0.f;

    auto load_chunk = [&](int s, int kc) {
        int c0 = kc * 32;
        uint32_t st = sb + s * STAGE;
        size_t aoff0 = ((size_t)(bm + r0i) * strideA + c0) * 2 + seg * 16;
        size_t aoff1 = ((size_t)(bm + r1i) * strideA + c0) * 2 + seg * 16;
        uint32_t so0 = r0i * PITCH + seg * 16;
        uint32_t so1 = r1i * PITCH + seg * 16;
        cp16(st + ST_A + so0, Ag + aoff0, p0);
        cp16(st + ST_A + so1, Ag + aoff1, p1);
        size_t boff0 = ((size_t)(nh * 128 + r0i) * KPAD + c0) * 2 + seg * 16;
        size_t boff1 = ((size_t)(nh * 128 + r1i) * KPAD + c0) * 2 + seg * 16;
        cp16(st + ST_B + so0, Bg + boff0, true);
        cp16(st + ST_B + so1, Bg + boff1, true);
    };

    load_chunk(0, 0);
    CP_COMMIT();
    if (nch > 1) load_chunk(1, 1);
    CP_COMMIT();

    uint32_t brow = (lane & 7) + ((lane >> 4) << 3);
    uint32_t bkof = ((lane >> 3) & 1) << 4;

    for (int kc = 0; kc < nch; kc++) {
        if (kc + 1 < nch) {
            CP_WAIT(1);
        } else {
            CP_WAIT(0);
        }
        __syncthreads();
        if (kc + 2 < nch) {
            load_chunk((kc + 2) % 3, kc + 2);
            CP_COMMIT();
        }

        uint32_t st = sb + (kc % 3) * STAGE;
#pragma unroll
        for (int kk = 0; kk < 2; kk++) {
            uint32_t afr[2][4], bfr[4][4];
#pragma unroll
            for (int mt = 0; mt < 2; mt++) {
                uint32_t ab = (uint32_t)((wm * 32 + mt * 16 + (lane & 15)) * PITCH
                               + kk * 32 + ((lane >> 4) << 4));
                LDSM_X4(afr[mt], st + ST_A + ab);
            }
#pragma unroll
            for (int nt2 = 0; nt2 < 4; nt2++) {
                uint32_t bb = (uint32_t)((wn * 64 + nt2 * 16 + brow) * PITCH + kk * 32 + bkof);
                LDSM_X4(bfr[nt2], st + ST_B + bb);
            }
#pragma unroll
            for (int mt = 0; mt < 2; mt++)
#pragma unroll
                for (int nt = 0; nt < 8; nt++) {
                    uint32_t b0 = bfr[nt >> 1][(nt & 1) * 2];
                    uint32_t b1 = bfr[nt >> 1][(nt & 1) * 2 + 1];
                    MMA_F16(acc[mt][nt], afr[mt], b0, b1);
                }
        }
        __syncthreads();
    }

    // epilogue: fp16 stores for both halves
    __half* outp = (nh == 0) ? d_projLh : d_projRh;
#pragma unroll
    for (int mt = 0; mt < 2; mt++) {
        int r0 = bm + wm * 32 + mt * 16 + g;
#pragma unroll
        for (int nt = 0; nt < 8; nt++) {
            int col = wn * 64 + nt * 8 + t4 * 2;
            if (r0 < M)
                *(__half2*)&outp[(size_t)r0 * 128 + col] =
                    __floats2half2_rn(acc[mt][nt][0], acc[mt][nt][1]);
            if (r0 + 8 < M)
                *(__half2*)&outp[(size_t)(r0 + 8) * 128 + col] =
                    __floats2half2_rn(acc[mt][nt][2], acc[mt][nt][3]);
        }
    }
}

// ---------------- aggregation + pooling (+ next-layer A write) ----------------
#define GNODES 16
__global__ void __launch_bounds__(512)
gather_combine(const float* __restrict__ b, const int* __restrict__ batch,
               int layer, int write_a) {
    __shared__ float sv[GNODES][CONV_OUT];
    __shared__ int   sbat[GNODES];

    int tid = threadIdx.x;
    int wid = tid >> 5;
    int lane = tid & 31;
    int node = blockIdx.x * GNODES + wid;
    bool valid = (node < N_NODES);

    if (valid) {
        int s0 = d_rowptr[node];
        int s1 = d_rowptr[node + 1];

        float acc0 = 0.f, acc1 = 0.f, acc2 = 0.f, acc3 = 0.f;
#pragma unroll 4
        for (int j = s0; j < s1; j++) {
            int nb = d_adj[j];
            uint2 v = *(const uint2*)&d_projLh[(size_t)nb * 128 + lane * 4];
            float2 f0 = __half22float2(*(__half2*)&v.x);
            float2 f1 = __half22float2(*(__half2*)&v.y);
            acc0 += f0.x; acc1 += f0.y; acc2 += f1.x; acc3 += f1.y;
        }
        float inv = 1.0f / fmaxf((float)(s1 - s0), 1.0f);
        uint2 rv = *(const uint2*)&d_projRh[(size_t)node * 128 + lane * 4];
        float2 r0 = __half22float2(*(__half2*)&rv.x);
        float2 r1 = __half22float2(*(__half2*)&rv.y);
        float4 bb = *(const float4*)&b[lane * 4];
        float hv[4];
        hv[0] = acc0 * inv + r0.x + bb.x;
        hv[1] = acc1 * inv + r0.y + bb.y;
        hv[2] = acc2 * inv + r1.x + bb.z;
        hv[3] = acc3 * inv + r1.y + bb.w;

        if (write_a) {
            __half2 h0 = __floats2half2_rn(hv[0], hv[1]);
            __half2 h1 = __floats2half2_rn(hv[2], hv[3]);
            size_t off = (size_t)node * STRIDE12 + lane * 4;
            *(__half2*)&d_A12[off]     = h0;
            *(__half2*)&d_A12[off + 2] = h1;
        }

        *(float4*)&sv[wid][lane * 4] = make_float4(hv[0], hv[1], hv[2], hv[3]);
        if (lane == 0) sbat[wid] = batch[node];
    } else {
        if (lane == 0) sbat[wid] = -1;
    }
    __syncthreads();

    if (tid < CONV_OUT) {
        int col = tid;
        int cur = -1;
        float mx = 0.f;
#pragma unroll
        for (int i = 0; i < GNODES; i++) {
            int bt = sbat[i];
            if (bt != cur) {
                if (cur >= 0)
                    atomicMax(&d_genc[cur * HCAT + layer * 128 + col], encf(mx));
                cur = bt;
                mx = -3.4e38f;
            }
            if (bt >= 0) mx = fmaxf(mx, sv[i][col]);
        }
        if (cur >= 0)
            atomicMax(&d_genc[cur * HCAT + layer * 128 + col], encf(mx));
    }
}

// ---------------- FC head ----------------
__global__ void fc_kernel(const float* __restrict__ Wfc1, const float* __restrict__ bfc1,
                          const float* __restrict__ Wfc2, const float* __restrict__ bfc2,
                          float* __restrict__ out) {
    __shared__ float g[HCAT];
    __shared__ float z[160];
    int gr = blockIdx.x, t = threadIdx.x;

    for (int i = t; i < HCAT; i += 160) g[i] = decf(d_genc[gr * HCAT + i]);
    __syncthreads();

    float acc = bfc1[t];
#pragma unroll 8
    for (int k = 0; k < HCAT; k++) acc += g[k] * Wfc1[k * 160 + t];
    z[t] = fmaxf(acc, 0.f);
    __syncthreads();

    if (t < 10) {
        float o = bfc2[t];
#pragma unroll 8
        for (int k = 0; k < 160; k++) o += z[k] * Wfc2[k * 10 + t];
        out[gr * 10 + t] = o;
    }
}

// ---------------- launch ----------------
extern "C" void kernel_launch(void* const* d_in, const int* in_sizes, int n_in,
                              void* d_out, int out_size) {
    const float* x     = (const float*)d_in[0];
    const int*   eidx  = (const int*)d_in[1];
    const int*   batch = (const int*)d_in[2];
    const float* info  = (const float*)d_in[3];
    const float* Wl[3] = { (const float*)d_in[4], (const float*)d_in[7],  (const float*)d_in[10] };
    const float* Wr[3] = { (const float*)d_in[5], (const float*)d_in[8],  (const float*)d_in[11] };
    const float* bb[3] = { (const float*)d_in[6], (const float*)d_in[9],  (const float*)d_in[12] };
    const float* Wfc1  = (const float*)d_in[13];
    const float* bfc1  = (const float*)d_in[14];
    const float* Wfc2  = (const float*)d_in[15];
    const float* bfc2  = (const float*)d_in[16];
    float* out = (float*)d_out;

    const int* src = eidx;
    const int* dst = eidx + N_EDGES;
    const int T = 256;

    cudaFuncSetAttribute(sage_gemm, cudaFuncAttributeMaxDynamicSharedMemorySize, SM_TOTAL);

    prep_fused<<<(int)((PREP_TOTAL + T - 1) / T), T>>>(x, info, batch,
        Wl[0], Wr[0], Wl[1], Wr[1], Wl[2], Wr[2]);
    deg_kernel<<<(N_EDGES + T - 1) / T, T>>>(dst);
    scan_kernel<<<1, 1024>>>();
    fill_kernel<<<(N_EDGES + T - 1) / T, T>>>(src, dst);

    __half *a0 = nullptr, *a12 = nullptr, *bp = nullptr;
    cudaGetSymbolAddress((void**)&a0, d_A0);
    cudaGetSymbolAddress((void**)&a12, d_A12);
    cudaGetSymbolAddress((void**)&bp, d_B);

    for (int layer = 0; layer < 3; layer++) {
        int K = (layer == 0) ? 128 : 160;
        int nch = K / 32;                       // exact K, no padded chunks
        const __half* A = (layer == 0) ? a0 : a12;
        int strideA = (layer == 0) ? 128 : STRIDE12;

        sage_gemm<<<dim3((N_NODES + 127) / 128, 2), 256, SM_TOTAL>>>(
            A, bp + layer * 256 * KPAD, strideA, nch);

        gather_combine<<<(N_NODES + GNODES - 1) / GNODES, 512>>>(bb[layer], batch, layer, layer < 2);
    }

    fc_kernel<<<NUM_GRAPHS, 160>>>(Wfc1, bfc1, Wfc2, bfc2, out);
    (void)in_sizes; (void)n_in; (void)out_size;
}